// round 3
// baseline (speedup 1.0000x reference)
#include <cuda_runtime.h>

#define NN 100000
#define NE 600000
#define HD 128

// ---------------- scratch (static device memory; no allocs) ----------------
static __device__ float g_x  [NN * HD];
static __device__ float g_y  [NN * HD];
static __device__ float g_agg[NN * HD];
static __device__ float g_p1 [NN * HD];
static __device__ float g_p2 [NN * HD];
static __device__ int   g_deg[NN];
static __device__ int   g_rowptr[NN + 1];
static __device__ int   g_cursor[NN];
static __device__ int   g_col[2 * NE];
static __device__ float g_invdeg[NN];

// ---------------- encoder: x = node_feats(8) @ W_enc + b_enc ----------------
__global__ void k_encoder(const float* __restrict__ ns, const float* __restrict__ pobs,
                          const int* __restrict__ pmask, const float* __restrict__ Wenc,
                          const float* __restrict__ benc, float* __restrict__ x, int n)
{
    __shared__ float sW[8 * HD];
    __shared__ float sb[HD];
    for (int i = threadIdx.x; i < 8 * HD; i += blockDim.x) sW[i] = Wenc[i];
    for (int i = threadIdx.x; i < HD; i += blockDim.x) sb[i] = benc[i];
    __syncthreads();
    int idx = blockIdx.x * blockDim.x + threadIdx.x;
    if (idx >= n * HD) return;
    int node = idx >> 7, h = idx & 127;
    float f0 = ns[node * 6 + 0], f1 = ns[node * 6 + 1], f2 = ns[node * 6 + 2];
    float f3 = ns[node * 6 + 3], f4 = ns[node * 6 + 4], f5 = ns[node * 6 + 5];
    float f6 = pobs[node];
    float f7 = (float)pmask[node];
    float o = sb[h];
    o += f0 * sW[0 * HD + h] + f1 * sW[1 * HD + h] + f2 * sW[2 * HD + h] + f3 * sW[3 * HD + h];
    o += f4 * sW[4 * HD + h] + f5 * sW[5 * HD + h] + f6 * sW[6 * HD + h] + f7 * sW[7 * HD + h];
    x[idx] = o;
}

// ---------------- CSR build ----------------
__global__ void k_zero_deg(int n)
{
    int i = blockIdx.x * blockDim.x + threadIdx.x;
    if (i < n) g_deg[i] = 0;
}

__global__ void k_deg(const int* __restrict__ ei, int ne)
{
    int e = blockIdx.x * blockDim.x + threadIdx.x;
    if (e >= ne) return;
    int s = ei[e], d = ei[ne + e];
    atomicAdd(&g_deg[s], 1);
    atomicAdd(&g_deg[d], 1);
}

// single-block inclusive scan over degrees -> rowptr, cursor, invdeg
__global__ void k_scan(int n)
{
    __shared__ int sh[1024];
    int t = threadIdx.x;
    int carry = 0;
    if (t == 0) g_rowptr[0] = 0;
    for (int base = 0; base < n; base += 1024) {
        int i = base + t;
        int v = (i < n) ? g_deg[i] : 0;
        sh[t] = v;
        __syncthreads();
        for (int off = 1; off < 1024; off <<= 1) {
            int tv = (t >= off) ? sh[t - off] : 0;
            __syncthreads();
            sh[t] += tv;
            __syncthreads();
        }
        if (i < n) {
            int incl = carry + sh[t];
            g_rowptr[i + 1] = incl;
            g_cursor[i] = incl - v;
            g_invdeg[i] = 1.0f / (float)(v > 0 ? v : 1);
        }
        carry += sh[1023];
        __syncthreads();
    }
}

__global__ void k_fill(const int* __restrict__ ei, int ne)
{
    int e = blockIdx.x * blockDim.x + threadIdx.x;
    if (e >= ne) return;
    int s = ei[e], d = ei[ne + e];
    int p = atomicAdd(&g_cursor[d], 1);
    g_col[p] = s;
    int q = atomicAdd(&g_cursor[s], 1);
    g_col[q] = d;
}

// ---------------- mean aggregation: one warp per node, float4/lane ----------------
__global__ void k_agg(const float* __restrict__ x, float* __restrict__ agg, int n)
{
    int w = (blockIdx.x * blockDim.x + threadIdx.x) >> 5;
    int lane = threadIdx.x & 31;
    if (w >= n) return;
    int beg = g_rowptr[w], end = g_rowptr[w + 1];
    float4 acc = make_float4(0.f, 0.f, 0.f, 0.f);
    for (int i = beg; i < end; i++) {
        int nb = g_col[i];
        float4 v = *reinterpret_cast<const float4*>(&x[(size_t)nb * HD + lane * 4]);
        acc.x += v.x; acc.y += v.y; acc.z += v.z; acc.w += v.w;
    }
    float sc = g_invdeg[w];
    acc.x *= sc; acc.y *= sc; acc.z *= sc; acc.w *= sc;
    *reinterpret_cast<float4*>(&agg[(size_t)w * HD + lane * 4]) = acc;
}

// ---------------- GNN layer GEMM: y = op(x@Ws + agg@Wn + b) ----------------
// 256 threads, 64 rows/block, 4x8 register tile, A-chunk transposed in smem,
// W streamed via LDG (L1-resident, 64KB each).
__global__ void k_layer(const float* __restrict__ x, const float* __restrict__ agg,
                        const float* __restrict__ Ws, const float* __restrict__ Wn,
                        const float* __restrict__ bias, float* __restrict__ y,
                        int n, int do_relu)
{
    __shared__ float sA[64 * 68];
    int tid = threadIdx.x;
    int row0 = blockIdx.x * 64;
    int rg = tid >> 4, cg = tid & 15;
    float acc[4][8];
#pragma unroll
    for (int i = 0; i < 4; i++)
#pragma unroll
        for (int j = 0; j < 8; j++) acc[i][j] = 0.f;

#pragma unroll 1
    for (int ch = 0; ch < 4; ch++) {
        const float* A = (ch < 2) ? x : agg;
        const float* W = (ch < 2) ? Ws : Wn;
        int kb = (ch & 1) * 64;
        __syncthreads();
        for (int idx = tid; idx < 64 * 64; idx += 256) {
            int k = idx & 63, r = idx >> 6;
            int gr = row0 + r;
            sA[k * 68 + r] = (gr < n) ? A[(size_t)gr * HD + kb + k] : 0.0f;
        }
        __syncthreads();
        const float4* W4 = reinterpret_cast<const float4*>(W);
#pragma unroll 4
        for (int k = 0; k < 64; k++) {
            float4 a = *reinterpret_cast<const float4*>(&sA[k * 68 + rg * 4]);
            int wr = (kb + k) * 32 + cg * 2;
            float4 w0 = __ldg(&W4[wr]);
            float4 w1 = __ldg(&W4[wr + 1]);
            float av[4] = {a.x, a.y, a.z, a.w};
            float wv[8] = {w0.x, w0.y, w0.z, w0.w, w1.x, w1.y, w1.z, w1.w};
#pragma unroll
            for (int i = 0; i < 4; i++)
#pragma unroll
                for (int j = 0; j < 8; j++) acc[i][j] += av[i] * wv[j];
        }
    }

    int c0 = cg * 8;
    float bv[8];
#pragma unroll
    for (int j = 0; j < 8; j++) bv[j] = __ldg(&bias[c0 + j]);
#pragma unroll
    for (int i = 0; i < 4; i++) {
        int r = row0 + rg * 4 + i;
        if (r < n) {
            float o[8];
#pragma unroll
            for (int j = 0; j < 8; j++) {
                float v = acc[i][j] + bv[j];
                o[j] = do_relu ? fmaxf(v, 0.f) : v;
            }
            float4* dst = reinterpret_cast<float4*>(&y[(size_t)r * HD + c0]);
            dst[0] = make_float4(o[0], o[1], o[2], o[3]);
            dst[1] = make_float4(o[4], o[5], o[6], o[7]);
        }
    }
}

// ---------------- edge-head precompute: Ao = x@W1[0:128], Bo = x@W1[128:256] ----------------
__global__ void k_prec(const float* __restrict__ x, const float* __restrict__ W1,
                       float* __restrict__ Ao, float* __restrict__ Bo, int n)
{
    __shared__ float sA[64 * 68];
    int tid = threadIdx.x;
    int row0 = blockIdx.x * 64;
    int rg = tid >> 4, cg = tid & 15;
    float acca[4][8], accb[4][8];
#pragma unroll
    for (int i = 0; i < 4; i++)
#pragma unroll
        for (int j = 0; j < 8; j++) { acca[i][j] = 0.f; accb[i][j] = 0.f; }

    const float4* W4 = reinterpret_cast<const float4*>(W1);
#pragma unroll 1
    for (int ch = 0; ch < 2; ch++) {
        int kb = ch * 64;
        __syncthreads();
        for (int idx = tid; idx < 64 * 64; idx += 256) {
            int k = idx & 63, r = idx >> 6;
            int gr = row0 + r;
            sA[k * 68 + r] = (gr < n) ? x[(size_t)gr * HD + kb + k] : 0.0f;
        }
        __syncthreads();
#pragma unroll 2
        for (int k = 0; k < 64; k++) {
            float4 a = *reinterpret_cast<const float4*>(&sA[k * 68 + rg * 4]);
            int rt = (kb + k) * 32 + cg * 2;
            int rb = (128 + kb + k) * 32 + cg * 2;
            float4 w0 = __ldg(&W4[rt]);
            float4 w1 = __ldg(&W4[rt + 1]);
            float4 u0 = __ldg(&W4[rb]);
            float4 u1 = __ldg(&W4[rb + 1]);
            float av[4] = {a.x, a.y, a.z, a.w};
            float wv[8] = {w0.x, w0.y, w0.z, w0.w, w1.x, w1.y, w1.z, w1.w};
            float uv[8] = {u0.x, u0.y, u0.z, u0.w, u1.x, u1.y, u1.z, u1.w};
#pragma unroll
            for (int i = 0; i < 4; i++)
#pragma unroll
                for (int j = 0; j < 8; j++) {
                    acca[i][j] += av[i] * wv[j];
                    accb[i][j] += av[i] * uv[j];
                }
        }
    }
    int c0 = cg * 8;
#pragma unroll
    for (int i = 0; i < 4; i++) {
        int r = row0 + rg * 4 + i;
        if (r < n) {
            float4* da = reinterpret_cast<float4*>(&Ao[(size_t)r * HD + c0]);
            da[0] = make_float4(acca[i][0], acca[i][1], acca[i][2], acca[i][3]);
            da[1] = make_float4(acca[i][4], acca[i][5], acca[i][6], acca[i][7]);
            float4* db = reinterpret_cast<float4*>(&Bo[(size_t)r * HD + c0]);
            db[0] = make_float4(accb[i][0], accb[i][1], accb[i][2], accb[i][3]);
            db[1] = make_float4(accb[i][4], accb[i][5], accb[i][6], accb[i][7]);
        }
    }
}

// ---------------- fused node heads: out = relu(x@W1+b1)@W2 + b2 (two heads) ----------------
__global__ void k_nodehead(const float* __restrict__ x,
                           const float* __restrict__ W1a, const float* __restrict__ b1a,
                           const float* __restrict__ W2a, const float* __restrict__ b2a,
                           const float* __restrict__ W1b, const float* __restrict__ b1b,
                           const float* __restrict__ W2b, const float* __restrict__ b2b,
                           float* __restrict__ outa, float* __restrict__ outb, int n)
{
    __shared__ float sA[64 * 68];
    int tid = threadIdx.x;
    int row0 = blockIdx.x * 64;
    int rg = tid >> 4, cg = tid & 15;
    float acca[4][8], accb[4][8];
#pragma unroll
    for (int i = 0; i < 4; i++)
#pragma unroll
        for (int j = 0; j < 8; j++) { acca[i][j] = 0.f; accb[i][j] = 0.f; }

    const float4* Wa4 = reinterpret_cast<const float4*>(W1a);
    const float4* Wb4 = reinterpret_cast<const float4*>(W1b);
#pragma unroll 1
    for (int ch = 0; ch < 2; ch++) {
        int kb = ch * 64;
        __syncthreads();
        for (int idx = tid; idx < 64 * 64; idx += 256) {
            int k = idx & 63, r = idx >> 6;
            int gr = row0 + r;
            sA[k * 68 + r] = (gr < n) ? x[(size_t)gr * HD + kb + k] : 0.0f;
        }
        __syncthreads();
#pragma unroll 2
        for (int k = 0; k < 64; k++) {
            float4 a = *reinterpret_cast<const float4*>(&sA[k * 68 + rg * 4]);
            int wr = (kb + k) * 32 + cg * 2;
            float4 w0 = __ldg(&Wa4[wr]);
            float4 w1 = __ldg(&Wa4[wr + 1]);
            float4 u0 = __ldg(&Wb4[wr]);
            float4 u1 = __ldg(&Wb4[wr + 1]);
            float av[4] = {a.x, a.y, a.z, a.w};
            float wv[8] = {w0.x, w0.y, w0.z, w0.w, w1.x, w1.y, w1.z, w1.w};
            float uv[8] = {u0.x, u0.y, u0.z, u0.w, u1.x, u1.y, u1.z, u1.w};
#pragma unroll
            for (int i = 0; i < 4; i++)
#pragma unroll
                for (int j = 0; j < 8; j++) {
                    acca[i][j] += av[i] * wv[j];
                    accb[i][j] += av[i] * uv[j];
                }
        }
    }
    // epilogue: bias + relu + dot(W2), block reduction over 16 col groups
    __syncthreads();
    float* sra = sA;
    float* srb = sA + 1024;
    int c0 = cg * 8;
    float b1av[8], b1bv[8], w2av[8], w2bv[8];
#pragma unroll
    for (int j = 0; j < 8; j++) {
        b1av[j] = __ldg(&b1a[c0 + j]); w2av[j] = __ldg(&W2a[c0 + j]);
        b1bv[j] = __ldg(&b1b[c0 + j]); w2bv[j] = __ldg(&W2b[c0 + j]);
    }
#pragma unroll
    for (int i = 0; i < 4; i++) {
        float pa = 0.f, pb = 0.f;
#pragma unroll
        for (int j = 0; j < 8; j++) {
            float h1 = fmaxf(acca[i][j] + b1av[j], 0.f);
            pa += h1 * w2av[j];
            float h2 = fmaxf(accb[i][j] + b1bv[j], 0.f);
            pb += h2 * w2bv[j];
        }
        int r = rg * 4 + i;
        sra[r * 16 + cg] = pa;
        srb[r * 16 + cg] = pb;
    }
    __syncthreads();
    if (tid < 64) {
        int grow = row0 + tid;
        if (grow < n) {
            float sa = 0.f, sb = 0.f;
#pragma unroll
            for (int c = 0; c < 16; c++) { sa += sra[tid * 16 + c]; sb += srb[tid * 16 + c]; }
            outa[grow] = sa + __ldg(&b2a[0]);
            outb[grow] = sb + __ldg(&b2b[0]);
        }
    }
}

// ---------------- edge heads: one warp per edge, gather A[src]+B[dst]+static part ----------------
__global__ void k_edge(const int* __restrict__ ei,
                       const float* __restrict__ estat, const float* __restrict__ qobs,
                       const int* __restrict__ qmask,
                       const float* __restrict__ erW1, const float* __restrict__ erb1,
                       const float* __restrict__ erW2, const float* __restrict__ erb2,
                       const float* __restrict__ eaW1, const float* __restrict__ eab1,
                       const float* __restrict__ eaW2, const float* __restrict__ eab2,
                       float* __restrict__ qhat, float* __restrict__ elog, int ne)
{
    __shared__ float sE[2][8 * HD];  // per head: rows 0-5 = W1[256+r], 6 = b1, 7 = W2
    int tid = threadIdx.x;
    for (int idx = tid; idx < 2 * 8 * HD; idx += blockDim.x) {
        int h = idx / (8 * HD);
        int rem = idx - h * 8 * HD;
        int r = rem >> 7, c = rem & 127;
        const float* W1 = h ? eaW1 : erW1;
        const float* b1 = h ? eab1 : erb1;
        const float* W2 = h ? eaW2 : erW2;
        float v;
        if (r < 6) v = W1[(256 + r) * HD + c];
        else if (r == 6) v = b1[c];
        else v = W2[c];
        sE[h][rem] = v;
    }
    __syncthreads();

    int w = (blockIdx.x * blockDim.x + tid) >> 5;
    int lane = tid & 31;
    if (w >= ne) return;
    int s = ei[w], d = ei[ne + w];
    float e0 = estat[w * 4 + 0], e1 = estat[w * 4 + 1];
    float e2 = estat[w * 4 + 2], e3 = estat[w * 4 + 3];
    float qo = qobs[w], qm = (float)qmask[w];
    int c = lane * 4;

    // head er: A in g_x, B in g_agg
    {
        const float* S = sE[0];
        float4 a = *reinterpret_cast<const float4*>(&g_x[(size_t)s * HD + c]);
        float4 b = *reinterpret_cast<const float4*>(&g_agg[(size_t)d * HD + c]);
        float av[4] = {a.x, a.y, a.z, a.w};
        float bv[4] = {b.x, b.y, b.z, b.w};
        float acc = 0.f;
#pragma unroll
        for (int t = 0; t < 4; t++) {
            int cc = c + t;
            float hv = av[t] + bv[t] + e0 * S[cc] + e1 * S[HD + cc] + e2 * S[2 * HD + cc]
                     + e3 * S[3 * HD + cc] + qo * S[4 * HD + cc] + qm * S[5 * HD + cc]
                     + S[6 * HD + cc];
            hv = fmaxf(hv, 0.f);
            acc += hv * S[7 * HD + cc];
        }
#pragma unroll
        for (int off = 16; off; off >>= 1) acc += __shfl_xor_sync(0xffffffffu, acc, off);
        if (lane == 0) qhat[w] = acc + __ldg(&erb2[0]);
    }
    // head ea: A in g_p1, B in g_p2
    {
        const float* S = sE[1];
        float4 a = *reinterpret_cast<const float4*>(&g_p1[(size_t)s * HD + c]);
        float4 b = *reinterpret_cast<const float4*>(&g_p2[(size_t)d * HD + c]);
        float av[4] = {a.x, a.y, a.z, a.w};
        float bv[4] = {b.x, b.y, b.z, b.w};
        float acc = 0.f;
#pragma unroll
        for (int t = 0; t < 4; t++) {
            int cc = c + t;
            float hv = av[t] + bv[t] + e0 * S[cc] + e1 * S[HD + cc] + e2 * S[2 * HD + cc]
                     + e3 * S[3 * HD + cc] + qo * S[4 * HD + cc] + qm * S[5 * HD + cc]
                     + S[6 * HD + cc];
            hv = fmaxf(hv, 0.f);
            acc += hv * S[7 * HD + cc];
        }
#pragma unroll
        for (int off = 16; off; off >>= 1) acc += __shfl_xor_sync(0xffffffffu, acc, off);
        if (lane == 0) elog[w] = acc + __ldg(&eab2[0]);
    }
}

// ---------------- launch ----------------
extern "C" void kernel_launch(void* const* d_in, const int* in_sizes, int n_in,
                              void* d_out, int out_size)
{
    const int*   ei           = (const int*)d_in[0];   // edge_index is int32 (jax x64 disabled)
    const float* node_static  = (const float*)d_in[1];
    const float* edge_static  = (const float*)d_in[2];
    const float* p_obs        = (const float*)d_in[3];
    const float* q_obs        = (const float*)d_in[4];
    const int*   p_mask       = (const int*)d_in[5];
    const int*   q_mask       = (const int*)d_in[6];
    const float* W_enc        = (const float*)d_in[7];
    const float* b_enc        = (const float*)d_in[8];
    const float* W_self       = (const float*)d_in[9];
    const float* W_neigh      = (const float*)d_in[10];
    const float* b_gnn        = (const float*)d_in[11];
    const float* nrW1 = (const float*)d_in[12]; const float* nrb1 = (const float*)d_in[13];
    const float* nrW2 = (const float*)d_in[14]; const float* nrb2 = (const float*)d_in[15];
    const float* naW1 = (const float*)d_in[16]; const float* nab1 = (const float*)d_in[17];
    const float* naW2 = (const float*)d_in[18]; const float* nab2 = (const float*)d_in[19];
    const float* erW1 = (const float*)d_in[20]; const float* erb1 = (const float*)d_in[21];
    const float* erW2 = (const float*)d_in[22]; const float* erb2 = (const float*)d_in[23];
    const float* eaW1 = (const float*)d_in[24]; const float* eab1 = (const float*)d_in[25];
    const float* eaW2 = (const float*)d_in[26]; const float* eab2 = (const float*)d_in[27];

    int n  = in_sizes[3];  // N (p_obs)
    int ne = in_sizes[4];  // E (q_obs)

    float* out   = (float*)d_out;
    float* p_hat = out;
    float* q_hat = out + n;
    float* nlog  = out + n + ne;
    float* elog  = out + 2 * n + ne;

    float *gx, *gy, *gagg, *gp1, *gp2;
    cudaGetSymbolAddress((void**)&gx,   g_x);
    cudaGetSymbolAddress((void**)&gy,   g_y);
    cudaGetSymbolAddress((void**)&gagg, g_agg);
    cudaGetSymbolAddress((void**)&gp1,  g_p1);
    cudaGetSymbolAddress((void**)&gp2,  g_p2);

    k_encoder<<<(n * HD + 255) / 256, 256>>>(node_static, p_obs, p_mask, W_enc, b_enc, gx, n);
    k_zero_deg<<<(n + 255) / 256, 256>>>(n);
    k_deg<<<(ne + 255) / 256, 256>>>(ei, ne);
    k_scan<<<1, 1024>>>(n);
    k_fill<<<(ne + 255) / 256, 256>>>(ei, ne);

    const float* xin = gx;
    float* xout = gy;
    for (int l = 0; l < 3; l++) {
        k_agg<<<(n * 32 + 255) / 256, 256>>>(xin, gagg, n);
        k_layer<<<(n + 63) / 64, 256>>>(xin, gagg, W_self + l * HD * HD, W_neigh + l * HD * HD,
                                        b_gnn + l * HD, xout, n, (l < 2) ? 1 : 0);
        const float* t = xin;
        xin = xout;
        xout = (float*)t;
    }
    const float* xf = xin;  // final node embeddings (g_y)

    k_nodehead<<<(n + 63) / 64, 256>>>(xf, nrW1, nrb1, nrW2, nrb2,
                                       naW1, nab1, naW2, nab2, p_hat, nlog, n);
    // edge-head per-node precompute: er -> (g_x, g_agg), ea -> (g_p1, g_p2)
    k_prec<<<(n + 63) / 64, 256>>>(xf, erW1, gx, gagg, n);
    k_prec<<<(n + 63) / 64, 256>>>(xf, eaW1, gp1, gp2, n);

    k_edge<<<(ne * 32 + 255) / 256, 256>>>(ei, edge_static, q_obs, q_mask,
                                           erW1, erb1, erW2, erb2,
                                           eaW1, eab1, eaW2, eab2,
                                           q_hat, elog, ne);
}